// round 10
// baseline (speedup 1.0000x reference)
#include <cuda_runtime.h>
#include <cuda_fp16.h>
#include <cstdint>

#define B_ 8
#define T_ 4096
#define D_ 512
#define H_ 512
#define M_ (B_*T_)      // 32768 rows
#define NC 256          // chunks per sequence
#define LC (T_/NC)      // 16 steps per chunk

// ----------------------------- scratch (device globals) -----------------------------
__device__ __half g_Wp[1024*512];       // [N/16 pairs][D/16][256] (paired 8n blocks, interleaved Wz/Wh)
__device__ __half2 g_CG[(size_t)M_*H_]; // (c,g) interleaved per (m,h)
__device__ float g_A[B_*NC*H_];
__device__ float g_S[B_*NC*H_];
__device__ float g_Hb[B_*NC*H_];

__device__ __forceinline__ float sigmoidf_(float x) { return 1.0f / (1.0f + __expf(-x)); }

__device__ __forceinline__ void mma_f16(float d[4], const uint32_t a[4], const uint32_t b[2]) {
    asm volatile(
        "mma.sync.aligned.m16n8k16.row.col.f32.f16.f16.f32 "
        "{%0,%1,%2,%3}, {%4,%5,%6,%7}, {%8,%9}, {%0,%1,%2,%3};\n"
        : "+f"(d[0]), "+f"(d[1]), "+f"(d[2]), "+f"(d[3])
        : "r"(a[0]), "r"(a[1]), "r"(a[2]), "r"(a[3]), "r"(b[0]), "r"(b[1]));
}

#define CP_ASYNC16(sa, gp) asm volatile("cp.async.cg.shared.global [%0], [%1], 16;" :: "r"(sa), "l"(__cvta_generic_to_global(gp)) : "memory")
#define CP_COMMIT()        asm volatile("cp.async.commit_group;" ::: "memory")
#define CP_WAIT1()         asm volatile("cp.async.wait_group 1;" ::: "memory")

__device__ __forceinline__ uint32_t smem_u32(const void* p) {
    uint32_t a;
    asm("{ .reg .u64 t; cvta.to.shared.u64 t, %1; cvt.u32.u64 %0, t; }" : "=r"(a) : "l"(p));
    return a;
}

__device__ __forceinline__ uint32_t pack2h(float a, float b) {
    __half2 h = __floats2half2_rn(a, b);
    return *reinterpret_cast<uint32_t*>(&h);
}

// ----------------------------- prep: W only (f32 -> fp16 paired fragments) -------------------
// Warp per (pair pb, kb): pair of 8-n fused blocks; fused row 2j = Wz[j], 2j+1 = Wh[j].
#define WPAIRS ((1024/16)*(D_/16))   // 2048

__global__ __launch_bounds__(256) void prep_kernel(
    const float* __restrict__ Wz, const float* __restrict__ Wh)
{
    const int wp   = blockIdx.x * 8 + (threadIdx.x >> 5);
    const int lane = threadIdx.x & 31;
    const int r = lane >> 2, c = lane & 3;
    if (wp >= WPAIRS) return;

    const int pb = wp >> 5;          // pair index 0..63
    const int kb = wp & 31;
    const int nfe = pb * 16 + r;         // even 8-block fused row
    const int nfo = pb * 16 + 8 + r;     // odd 8-block fused row
    const float* We = (nfe & 1) ? (Wh + (size_t)(nfe >> 1) * D_) : (Wz + (size_t)(nfe >> 1) * D_);
    const float* Wo = (nfo & 1) ? (Wh + (size_t)(nfo >> 1) * D_) : (Wz + (size_t)(nfo >> 1) * D_);
    uint4 v;
    v.x = pack2h(We[kb*16 + 2*c],     We[kb*16 + 2*c + 1]);
    v.y = pack2h(We[kb*16 + 2*c + 8], We[kb*16 + 2*c + 9]);
    v.z = pack2h(Wo[kb*16 + 2*c],     Wo[kb*16 + 2*c + 1]);
    v.w = pack2h(Wo[kb*16 + 2*c + 8], Wo[kb*16 + 2*c + 9]);
    reinterpret_cast<uint4*>(g_Wp)[(size_t)wp * 32 + lane] = v;
}

// ----------------------------- GEMM + activation + fused chunk-reduce -----------------------
// CTA 128m x 128n; stage K=64; 8 stages; NBUF=3 (96KB, 2 CTAs/SM).
// A loaded from f32 x via LDG.128 -> cvt -> STS (fragment layout); B via cp.async (prepacked).
#define KSTAGES 8
#define NBUF 3
#define A_STAGE_BYTES 16384
#define B_STAGE_BYTES 16384
#define STAGE_BYTES (A_STAGE_BYTES + B_STAGE_BYTES)
#define GEMM_SMEM (NBUF*STAGE_BYTES + 1024)   // 99328
#define SCG_STRIDE 68

__global__ __launch_bounds__(256, 2) void gemm_act_kernel(
    const float* __restrict__ xg,
    const float* __restrict__ bz, const float* __restrict__ bh)
{
    extern __shared__ char dyn[];
    float* sBias = reinterpret_cast<float*>(dyn + NBUF * STAGE_BYTES);
    const uint32_t sbase = smem_u32(dyn);

    const int tid  = threadIdx.x;
    const int wid  = tid >> 5;
    const int lane = tid & 31;
    const int wm = wid >> 2;
    const int wn = wid & 3;

    const int bn = blockIdx.x;   // 0..7 over fused-interleaved N=1024 (64 h each)
    const int bm = blockIdx.y;   // 0..255
    const int m0 = bm * 128;
    const int pb0 = bn * 8;

    // A loader role: 8 threads per row-slice, sub = k-chunk of 8 f32
    const int sub   = tid & 7;       // 0..7
    const int rbase = tid >> 3;      // 0..31 (rows rbase + 32p)

    if (tid < 128) {
        const int h = bn * 64 + (tid >> 1);
        sBias[tid] = (tid & 1) ? bh[h] : bz[h];
    }

    float acc[4][4][4];
    #pragma unroll
    for (int i = 0; i < 4; i++)
        #pragma unroll
        for (int j = 0; j < 4; j++)
            #pragma unroll
            for (int q = 0; q < 4; q++) acc[i][j][q] = 0.f;

    // ---- A: LDG f32 (coalesced) ----
    float4 xa[8];
    auto ldgA = [&](int s) {
        const float* gp = xg + (size_t)(m0 + rbase) * D_ + s * 64 + sub * 8;
        #pragma unroll
        for (int p = 0; p < 4; p++) {
            xa[2*p]   = *reinterpret_cast<const float4*>(gp + (size_t)p * 32 * D_);
            xa[2*p+1] = *reinterpret_cast<const float4*>(gp + (size_t)p * 32 * D_ + 4);
        }
    };
    // ---- A: cvt + STS into fragment layout ----
    auto stsA = [&](int buf) {
        const uint32_t stA = sbase + buf * STAGE_BYTES;
        #pragma unroll
        for (int p = 0; p < 4; p++) {
            const int r  = rbase + 32 * p;
            const int mb = r >> 4;
            const int rl = r & 15;
            const int r8 = rl & 7;
            const int hi = rl >> 3;
            const float* f = reinterpret_cast<const float*>(&xa[2*p]);
            #pragma unroll
            for (int j = 0; j < 4; j++) {
                const uint32_t h2 = pack2h(f[2*j], f[2*j+1]);
                const int cp  = sub * 4 + j;      // colpair 0..31
                const int kbi = cp >> 3;
                const int c0  = cp & 7;
                const uint32_t addr = stA + (mb * 4 + kbi) * 512
                                    + (r8 * 4 + (c0 & 3)) * 16
                                    + (hi + 2 * (c0 >> 2)) * 4;
                asm volatile("st.shared.b32 [%0], %1;" :: "r"(addr), "r"(h2));
            }
        }
    };
    // ---- B: cp.async (prepacked fp16) ----
    auto cpB = [&](int s, int buf) {
        const int kb0 = s * 4;
        const uint32_t stB = sbase + buf * STAGE_BYTES + A_STAGE_BYTES;
        #pragma unroll
        for (int i = 0; i < 4; i++) {
            const int seg = tid + i * 256;
            const int pbi = seg >> 7;
            const int w   = seg & 127;
            const __half* gp = g_Wp + ((size_t)(pb0 + pbi) * 32 + kb0) * 256 + w * 8;
            CP_ASYNC16(stB + seg * 16, gp);
        }
    };

    // prologue: stages 0,1
    ldgA(0); stsA(0);
    ldgA(1); stsA(1);
    cpB(0, 0); CP_COMMIT();
    cpB(1, 1); CP_COMMIT();

    int bufC = 0;           // buffer of stage s
    for (int s = 0; s < KSTAGES; s++) {
        CP_WAIT1();
        __syncthreads();
        const int bufN = (bufC == 2) ? 0 : bufC + 1;       // s+1
        const int bufL = (bufN == 2) ? 0 : bufN + 1;       // s+2
        if (s + 2 < KSTAGES) { ldgA(s + 2); cpB(s + 2, bufL); }
        CP_COMMIT();

        const char* stA = dyn + bufC * STAGE_BYTES;
        const char* stB = stA + A_STAGE_BYTES;

        #pragma unroll
        for (int ks = 0; ks < 4; ks++) {
            uint32_t af[4][4];
            uint32_t bf[4][2];
            #pragma unroll
            for (int mt = 0; mt < 4; mt++) {
                const int mb = wm * 4 + mt;
                const uint4 v = *reinterpret_cast<const uint4*>(stA + (mb * 4 + ks) * 512 + lane * 16);
                af[mt][0] = v.x; af[mt][1] = v.y; af[mt][2] = v.z; af[mt][3] = v.w;
            }
            #pragma unroll
            for (int i = 0; i < 2; i++) {
                const int pbl = wn * 2 + i;
                const uint4 v = *reinterpret_cast<const uint4*>(stB + (pbl * 4 + ks) * 512 + lane * 16);
                bf[2*i][0]   = v.x; bf[2*i][1]   = v.y;
                bf[2*i+1][0] = v.z; bf[2*i+1][1] = v.w;
            }
            #pragma unroll
            for (int mt = 0; mt < 4; mt++)
                #pragma unroll
                for (int nt = 0; nt < 4; nt++)
                    mma_f16(acc[mt][nt], af[mt], bf[nt]);
        }

        if (s + 2 < KSTAGES) stsA(bufL);   // barrier at next iter top publishes it
        bufC = bufN;
    }

    __syncthreads();   // all warps done reading stage smem before sCG overwrite

    // ---- epilogue: bias + activation; (c,g) -> global half2 + smem stage ----
    uint32_t* sCG = reinterpret_cast<uint32_t*>(dyn);   // [128][SCG_STRIDE] u32 (half2)
    const int row0 = wm * 64 + (lane >> 2);
    const int col0 = wn * 32 + 2 * (lane & 3);

    #pragma unroll
    for (int mt = 0; mt < 4; mt++) {
        #pragma unroll
        for (int nt = 0; nt < 4; nt++) {
            const int cl = col0 + nt * 8;
            const int hl = cl >> 1;
            const float b0v = sBias[cl];
            const float b1v = sBias[cl + 1];
            #pragma unroll
            for (int half = 0; half < 2; half++) {
                const int rl = row0 + mt * 16 + half * 8;
                const float v0 = acc[mt][nt][half * 2 + 0] + b0v;
                const float v1 = acc[mt][nt][half * 2 + 1] + b1v;
                const float c = sigmoidf_(-v0);
                const float g = (v1 >= 0.f) ? (v1 + 0.5f) : sigmoidf_(v1);
                const uint32_t cg = pack2h(c, g);
                reinterpret_cast<uint32_t*>(g_CG)[(size_t)(m0 + rl) * H_ + bn * 64 + hl] = cg;
                sCG[rl * SCG_STRIDE + hl] = cg;
            }
        }
    }
    __syncthreads();

    // ---- fused chunk reduce: tile = 8 chunks of 16 rows; 2 chunks per thread ----
    {
        const int h    = tid & 63;
        const int slot = tid >> 6;          // 0..3
        const int b    = bm >> 5;
        const int hg   = bn * 64 + h;
        #pragma unroll
        for (int i = 0; i < 2; i++) {
            const int c = slot * 2 + i;     // chunk within tile 0..7
            float A = 1.f, S = 0.f;
            const int t0 = c * 16;
            #pragma unroll
            for (int t = 0; t < 16; t++) {
                const __half2 cgh = *reinterpret_cast<const __half2*>(&sCG[(t0 + t) * SCG_STRIDE + h]);
                const float2 f = __half22float2(cgh);
                S = f.x * S + (1.f - f.x) * f.y;
                A *= f.x;
            }
            const int chg = ((bm & 31) << 3) | c;    // global chunk 0..255
            g_A[(b * NC + chg) * H_ + hg] = A;
            g_S[(b * NC + chg) * H_ + hg] = S;
        }
    }
}

// ----------------------------- scan phase B: warp-parallel chunk combine ----------------------
// One warp per (b, h-quad). Lane l covers chunks 8l..8l+7.
__global__ __launch_bounds__(256) void scan_phaseB(const float* __restrict__ h0)
{
    const int q    = blockIdx.x * 8 + (threadIdx.x >> 5);   // 0..1023
    const int lane = threadIdx.x & 31;
    const int b  = q >> 7;
    const int h4 = q & 127;

    const float4* A4 = reinterpret_cast<const float4*>(g_A);
    const float4* S4 = reinterpret_cast<const float4*>(g_S);
    float4* Hb4 = reinterpret_cast<float4*>(g_Hb);

    const int ob = (b * NC + 8 * lane) * 128 + h4;
    float4 Ai[8], Si[8];
    #pragma unroll
    for (int i = 0; i < 8; i++) {
        Ai[i] = A4[ob + i * 128];
        Si[i] = S4[ob + i * 128];
    }

    float4 Ap = Ai[0], Sp = Si[0];
    #pragma unroll
    for (int i = 1; i < 8; i++) {
        Sp.x = Ai[i].x*Sp.x + Si[i].x;  Ap.x *= Ai[i].x;
        Sp.y = Ai[i].y*Sp.y + Si[i].y;  Ap.y *= Ai[i].y;
        Sp.z = Ai[i].z*Sp.z + Si[i].z;  Ap.z *= Ai[i].z;
        Sp.w = Ai[i].w*Sp.w + Si[i].w;  Ap.w *= Ai[i].w;
    }

    #pragma unroll
    for (int d = 1; d < 32; d <<= 1) {
        float4 Au, Su;
        Au.x = __shfl_up_sync(0xFFFFFFFFu, Ap.x, d);
        Au.y = __shfl_up_sync(0xFFFFFFFFu, Ap.y, d);
        Au.z = __shfl_up_sync(0xFFFFFFFFu, Ap.z, d);
        Au.w = __shfl_up_sync(0xFFFFFFFFu, Ap.w, d);
        Su.x = __shfl_up_sync(0xFFFFFFFFu, Sp.x, d);
        Su.y = __shfl_up_sync(0xFFFFFFFFu, Sp.y, d);
        Su.z = __shfl_up_sync(0xFFFFFFFFu, Sp.z, d);
        Su.w = __shfl_up_sync(0xFFFFFFFFu, Sp.w, d);
        if (lane >= d) {
            Sp.x = Ap.x*Su.x + Sp.x;  Ap.x *= Au.x;
            Sp.y = Ap.y*Su.y + Sp.y;  Ap.y *= Au.y;
            Sp.z = Ap.z*Su.z + Sp.z;  Ap.z *= Au.z;
            Sp.w = Ap.w*Su.w + Sp.w;  Ap.w *= Au.w;
        }
    }

    float4 Ae, Se;
    Ae.x = __shfl_up_sync(0xFFFFFFFFu, Ap.x, 1);
    Ae.y = __shfl_up_sync(0xFFFFFFFFu, Ap.y, 1);
    Ae.z = __shfl_up_sync(0xFFFFFFFFu, Ap.z, 1);
    Ae.w = __shfl_up_sync(0xFFFFFFFFu, Ap.w, 1);
    Se.x = __shfl_up_sync(0xFFFFFFFFu, Sp.x, 1);
    Se.y = __shfl_up_sync(0xFFFFFFFFu, Sp.y, 1);
    Se.z = __shfl_up_sync(0xFFFFFFFFu, Sp.z, 1);
    Se.w = __shfl_up_sync(0xFFFFFFFFu, Sp.w, 1);
    if (lane == 0) {
        Ae = make_float4(1.f,1.f,1.f,1.f);
        Se = make_float4(0.f,0.f,0.f,0.f);
    }

    const float4 v = reinterpret_cast<const float4*>(h0)[b * 128 + h4];
    float4 st;
    st.x = (v.x >= 0.f) ? (v.x + 0.5f) : sigmoidf_(v.x);
    st.y = (v.y >= 0.f) ? (v.y + 0.5f) : sigmoidf_(v.y);
    st.z = (v.z >= 0.f) ? (v.z + 0.5f) : sigmoidf_(v.z);
    st.w = (v.w >= 0.f) ? (v.w + 0.5f) : sigmoidf_(v.w);

    st.x = Ae.x*st.x + Se.x;
    st.y = Ae.y*st.y + Se.y;
    st.z = Ae.z*st.z + Se.z;
    st.w = Ae.w*st.w + Se.w;

    #pragma unroll
    for (int i = 0; i < 8; i++) {
        Hb4[ob + i * 128] = st;
        st.x = Ai[i].x*st.x + Si[i].x;
        st.y = Ai[i].y*st.y + Si[i].y;
        st.z = Ai[i].z*st.z + Si[i].z;
        st.w = Ai[i].w*st.w + Si[i].w;
    }
}

// ----------------------------- scan phase C: rescan + output -----------------------------
__global__ __launch_bounds__(256) void scan_phaseC(float* __restrict__ out)
{
    const int idx = blockIdx.x * 256 + threadIdx.x;     // 0 .. 262143
    const int h4 = idx & 127;
    const int ch = (idx >> 7) & (NC - 1);
    const int b  = idx >> 15;
    const uint4* CG4 = reinterpret_cast<const uint4*>(g_CG);
    float4* O4 = reinterpret_cast<float4*>(out);
    size_t p = ((size_t)(b * T_ + ch * LC) * H_) / 4 + h4;

    float4 st = reinterpret_cast<const float4*>(g_Hb)[(b * NC + ch) * 128 + h4];
    #pragma unroll 4
    for (int t = 0; t < LC; t++, p += H_/4) {
        const uint4 u = CG4[p];
        const float2 a0 = __half22float2(*reinterpret_cast<const __half2*>(&u.x));
        const float2 a1 = __half22float2(*reinterpret_cast<const __half2*>(&u.y));
        const float2 a2 = __half22float2(*reinterpret_cast<const __half2*>(&u.z));
        const float2 a3 = __half22float2(*reinterpret_cast<const __half2*>(&u.w));
        st.x = a0.x*st.x + (1.f-a0.x)*a0.y;
        st.y = a1.x*st.y + (1.f-a1.x)*a1.y;
        st.z = a2.x*st.z + (1.f-a2.x)*a2.y;
        st.w = a3.x*st.w + (1.f-a3.x)*a3.y;
        O4[p] = st;
    }
}

extern "C" void kernel_launch(void* const* d_in, const int* in_sizes, int n_in,
                              void* d_out, int out_size)
{
    const float* x  = (const float*)d_in[0];
    const float* h0 = (const float*)d_in[1];
    const float* Wz = (const float*)d_in[2];
    const float* bz = (const float*)d_in[3];
    const float* Wh = (const float*)d_in[4];
    const float* bh = (const float*)d_in[5];
    float* out = (float*)d_out;

    cudaFuncSetAttribute(gemm_act_kernel, cudaFuncAttributeMaxDynamicSharedMemorySize, GEMM_SMEM);

    prep_kernel<<<WPAIRS / 8, 256>>>(Wz, Wh);
    gemm_act_kernel<<<dim3(8, 256), 256, GEMM_SMEM>>>(x, bz, bh);
    scan_phaseB<<<128, 256>>>(h0);
    scan_phaseC<<<1024, 256>>>(out);
}

// round 11
// speedup vs baseline: 1.4121x; 1.4121x over previous
#include <cuda_runtime.h>
#include <cuda_fp16.h>
#include <cstdint>

#define B_ 8
#define T_ 4096
#define D_ 512
#define H_ 512
#define M_ (B_*T_)      // 32768 rows
#define NC 128          // chunks per sequence
#define LC (T_/NC)      // 32 steps per chunk

// ----------------------------- scratch (device globals) -----------------------------
__device__ __half g_Xp[(size_t)M_*D_];  // [M/16][D/16][256] (16m x 16k blocks, fragment order)
__device__ __half g_Wp[1024*512];       // [N/16 pairs][D/16][256] (paired 8n blocks, interleaved Wz/Wh)
__device__ __half2 g_CG[(size_t)M_*H_]; // (c,g) interleaved per (m,h)
__device__ float g_A[B_*NC*H_];
__device__ float g_S[B_*NC*H_];
__device__ float g_Hb[B_*NC*H_];

__device__ __forceinline__ float sigmoidf_(float x) { return 1.0f / (1.0f + __expf(-x)); }

__device__ __forceinline__ void mma_f16(float d[4], const uint32_t a[4], const uint32_t b[2]) {
    asm volatile(
        "mma.sync.aligned.m16n8k16.row.col.f32.f16.f16.f32 "
        "{%0,%1,%2,%3}, {%4,%5,%6,%7}, {%8,%9}, {%0,%1,%2,%3};\n"
        : "+f"(d[0]), "+f"(d[1]), "+f"(d[2]), "+f"(d[3])
        : "r"(a[0]), "r"(a[1]), "r"(a[2]), "r"(a[3]), "r"(b[0]), "r"(b[1]));
}

#define CP_ASYNC16(sa, gp) asm volatile("cp.async.cg.shared.global [%0], [%1], 16;" :: "r"(sa), "l"(__cvta_generic_to_global(gp)) : "memory")
#define CP_COMMIT()        asm volatile("cp.async.commit_group;" ::: "memory")
#define CP_WAIT1()         asm volatile("cp.async.wait_group 1;" ::: "memory")

__device__ __forceinline__ uint32_t smem_u32(const void* p) {
    uint32_t a;
    asm("{ .reg .u64 t; cvta.to.shared.u64 t, %1; cvt.u32.u64 %0, t; }" : "=r"(a) : "l"(p));
    return a;
}

__device__ __forceinline__ uint32_t pack2h(float a, float b) {
    __half2 h = __floats2half2_rn(a, b);
    return *reinterpret_cast<uint32_t*>(&h);
}

// ----------------------------- prep: f32 -> fp16 fragment pack -----------------------------
#define XBLOCKS ((M_/16)*(D_/16))    // 65536
#define WPAIRS ((1024/16)*(D_/16))   // 2048

__global__ __launch_bounds__(256) void prep_kernel(
    const float* __restrict__ x, const float* __restrict__ Wz, const float* __restrict__ Wh)
{
    const int gw   = blockIdx.x * 8 + (threadIdx.x >> 5);
    const int lane = threadIdx.x & 31;
    const int r = lane >> 2, c = lane & 3;

    if (gw < XBLOCKS) {
        const int mb = gw >> 5;
        const int kb = gw & 31;
        const float* xp = x + (size_t)(mb * 16) * D_ + kb * 16;
        uint4 v;
        v.x = pack2h(xp[(size_t)r * D_ + 2*c],       xp[(size_t)r * D_ + 2*c + 1]);
        v.y = pack2h(xp[(size_t)(r+8) * D_ + 2*c],   xp[(size_t)(r+8) * D_ + 2*c + 1]);
        v.z = pack2h(xp[(size_t)r * D_ + 2*c + 8],   xp[(size_t)r * D_ + 2*c + 9]);
        v.w = pack2h(xp[(size_t)(r+8) * D_ + 2*c+8], xp[(size_t)(r+8) * D_ + 2*c + 9]);
        reinterpret_cast<uint4*>(g_Xp)[(size_t)gw * 32 + lane] = v;
    } else {
        const int wp = gw - XBLOCKS;     // 0..2047
        const int pb = wp >> 5;
        const int kb = wp & 31;
        const int nfe = pb * 16 + r;
        const int nfo = pb * 16 + 8 + r;
        const float* We = (nfe & 1) ? (Wh + (size_t)(nfe >> 1) * D_) : (Wz + (size_t)(nfe >> 1) * D_);
        const float* Wo = (nfo & 1) ? (Wh + (size_t)(nfo >> 1) * D_) : (Wz + (size_t)(nfo >> 1) * D_);
        uint4 v;
        v.x = pack2h(We[kb*16 + 2*c],     We[kb*16 + 2*c + 1]);
        v.y = pack2h(We[kb*16 + 2*c + 8], We[kb*16 + 2*c + 9]);
        v.z = pack2h(Wo[kb*16 + 2*c],     Wo[kb*16 + 2*c + 1]);
        v.w = pack2h(Wo[kb*16 + 2*c + 8], Wo[kb*16 + 2*c + 9]);
        reinterpret_cast<uint4*>(g_Wp)[(size_t)wp * 32 + lane] = v;
    }
}

// ----------------------------- GEMM + activation + fused chunk-reduce -----------------------
// CTA 128m x 128n; stage K=64; 8 stages; NBUF=3 (96KB, 2 CTAs/SM).
#define KSTAGES 8
#define NBUF 3
#define A_STAGE_BYTES 16384
#define B_STAGE_BYTES 16384
#define STAGE_BYTES (A_STAGE_BYTES + B_STAGE_BYTES)
#define GEMM_SMEM (NBUF*STAGE_BYTES + 1024)   // 99328
#define SCG_STRIDE 68                          // u32 per row (pad: 68*4=272=16*17, 16B aligned rows)

__global__ __launch_bounds__(256, 2) void gemm_act_kernel(
    const float* __restrict__ bz, const float* __restrict__ bh)
{
    extern __shared__ char dyn[];
    float* sBias = reinterpret_cast<float*>(dyn + NBUF * STAGE_BYTES);
    const uint32_t sbase = smem_u32(dyn);

    const int tid  = threadIdx.x;
    const int wid  = tid >> 5;
    const int lane = tid & 31;
    const int wm = wid >> 2;
    const int wn = wid & 3;

    const int bn = blockIdx.x;   // 0..7 over fused-interleaved N=1024 (64 h each)
    const int bm = blockIdx.y;   // 0..255
    const int m0 = bm * 128;
    const int mb0 = bm * 8;
    const int pb0 = bn * 8;

    if (tid < 128) {
        const int h = bn * 64 + (tid >> 1);
        sBias[tid] = (tid & 1) ? bh[h] : bz[h];
    }

    float acc[4][4][4];
    #pragma unroll
    for (int i = 0; i < 4; i++)
        #pragma unroll
        for (int j = 0; j < 4; j++)
            #pragma unroll
            for (int q = 0; q < 4; q++) acc[i][j][q] = 0.f;

    auto load_stage = [&](int s, int buf) {
        const int kb0 = s * 4;
        const uint32_t stA = sbase + buf * STAGE_BYTES;
        const uint32_t stB = stA + A_STAGE_BYTES;
        #pragma unroll
        for (int i = 0; i < 4; i++) {            // A: 1024 segs of 16B
            const int seg = tid + i * 256;
            const int mbi = seg >> 7;
            const int w   = seg & 127;
            const __half* gp = g_Xp + ((size_t)(mb0 + mbi) * 32 + kb0) * 256 + w * 8;
            CP_ASYNC16(stA + seg * 16, gp);
        }
        #pragma unroll
        for (int i = 0; i < 4; i++) {            // B: 1024 segs of 16B
            const int seg = tid + i * 256;
            const int pbi = seg >> 7;
            const int w   = seg & 127;
            const __half* gp = g_Wp + ((size_t)(pb0 + pbi) * 32 + kb0) * 256 + w * 8;
            CP_ASYNC16(stB + seg * 16, gp);
        }
    };

    load_stage(0, 0); CP_COMMIT();
    load_stage(1, 1); CP_COMMIT();

    int bufC = 0;
    int bufL = 2;
    for (int s = 0; s < KSTAGES; s++) {
        CP_WAIT1();
        __syncthreads();
        if (s + 2 < KSTAGES) load_stage(s + 2, bufL);
        CP_COMMIT();

        const char* stA = dyn + bufC * STAGE_BYTES;
        const char* stB = stA + A_STAGE_BYTES;
        bufL = bufC;
        bufC = (bufC == 2) ? 0 : bufC + 1;

        #pragma unroll
        for (int ks = 0; ks < 4; ks++) {
            uint32_t af[4][4];
            uint32_t bf[4][2];
            #pragma unroll
            for (int mt = 0; mt < 4; mt++) {
                const int mb = wm * 4 + mt;
                const uint4 v = *reinterpret_cast<const uint4*>(stA + (mb * 4 + ks) * 512 + lane * 16);
                af[mt][0] = v.x; af[mt][1] = v.y; af[mt][2] = v.z; af[mt][3] = v.w;
            }
            #pragma unroll
            for (int i = 0; i < 2; i++) {
                const int pbl = wn * 2 + i;
                const uint4 v = *reinterpret_cast<const uint4*>(stB + (pbl * 4 + ks) * 512 + lane * 16);
                bf[2*i][0]   = v.x; bf[2*i][1]   = v.y;
                bf[2*i+1][0] = v.z; bf[2*i+1][1] = v.w;
            }
            #pragma unroll
            for (int mt = 0; mt < 4; mt++)
                #pragma unroll
                for (int nt = 0; nt < 4; nt++)
                    mma_f16(acc[mt][nt], af[mt], bf[nt]);
        }
    }

    __syncthreads();   // all warps done reading stage smem before sCG overwrite

    // ---- epilogue: bias + activation -> sCG (smem only) ----
    uint32_t* sCG = reinterpret_cast<uint32_t*>(dyn);   // [128][SCG_STRIDE] u32 (half2)
    const int row0 = wm * 64 + (lane >> 2);
    const int col0 = wn * 32 + 2 * (lane & 3);

    #pragma unroll
    for (int mt = 0; mt < 4; mt++) {
        #pragma unroll
        for (int nt = 0; nt < 4; nt++) {
            const int cl = col0 + nt * 8;
            const int hl = cl >> 1;
            const float b0v = sBias[cl];
            const float b1v = sBias[cl + 1];
            #pragma unroll
            for (int half = 0; half < 2; half++) {
                const int rl = row0 + mt * 16 + half * 8;
                const float v0 = acc[mt][nt][half * 2 + 0] + b0v;
                const float v1 = acc[mt][nt][half * 2 + 1] + b1v;
                const float c = sigmoidf_(-v0);
                const float g = (v1 >= 0.f) ? (v1 + 0.5f) : sigmoidf_(v1);
                sCG[rl * SCG_STRIDE + hl] = pack2h(c, g);
            }
        }
    }
    __syncthreads();

    // ---- coalesced g_CG store from sCG: 2048 uint4, 8 per thread ----
    {
        uint4* CGg = reinterpret_cast<uint4*>(g_CG);
        #pragma unroll
        for (int i = 0; i < 8; i++) {
            const int idx = tid + i * 256;       // 0..2047
            const int rl  = idx >> 4;            // row 0..127
            const int q   = idx & 15;            // uint4 within 64 h
            const uint4 v = *reinterpret_cast<const uint4*>(&sCG[rl * SCG_STRIDE + q * 4]);
            CGg[((size_t)(m0 + rl) * 512 + bn * 64) / 4 + q] = v;
        }
    }

    // ---- fused chunk reduce: tile = 4 chunks of 32 rows; one (chunk,h) per thread ----
    {
        const int h   = tid & 63;
        const int seg = tid >> 6;
        float A = 1.f, S = 0.f;
        const int t0 = seg * 32;
        #pragma unroll 8
        for (int t = 0; t < 32; t++) {
            const __half2 cgh = *reinterpret_cast<const __half2*>(&sCG[(t0 + t) * SCG_STRIDE + h]);
            const float2 f = __half22float2(cgh);
            S = f.x * S + (1.f - f.x) * f.y;
            A *= f.x;
        }
        const int b   = bm >> 5;
        const int chg = ((bm & 31) << 2) | seg;
        const int hg  = bn * 64 + h;
        g_A[(b * NC + chg) * H_ + hg] = A;
        g_S[(b * NC + chg) * H_ + hg] = S;
    }
}

// ----------------------------- scan phase B: warp-parallel chunk combine ----------------------
__global__ __launch_bounds__(256) void scan_phaseB(const float* __restrict__ h0)
{
    const int q    = blockIdx.x * 8 + (threadIdx.x >> 5);   // 0..1023
    const int lane = threadIdx.x & 31;
    const int b  = q >> 7;
    const int h4 = q & 127;

    const float4* A4 = reinterpret_cast<const float4*>(g_A);
    const float4* S4 = reinterpret_cast<const float4*>(g_S);
    float4* Hb4 = reinterpret_cast<float4*>(g_Hb);

    const int ob = (b * NC + 4 * lane) * 128 + h4;
    float4 Ai[4], Si[4];
    #pragma unroll
    for (int i = 0; i < 4; i++) {
        Ai[i] = A4[ob + i * 128];
        Si[i] = S4[ob + i * 128];
    }

    float4 Ap = Ai[0], Sp = Si[0];
    #pragma unroll
    for (int i = 1; i < 4; i++) {
        Sp.x = Ai[i].x*Sp.x + Si[i].x;  Ap.x *= Ai[i].x;
        Sp.y = Ai[i].y*Sp.y + Si[i].y;  Ap.y *= Ai[i].y;
        Sp.z = Ai[i].z*Sp.z + Si[i].z;  Ap.z *= Ai[i].z;
        Sp.w = Ai[i].w*Sp.w + Si[i].w;  Ap.w *= Ai[i].w;
    }

    #pragma unroll
    for (int d = 1; d < 32; d <<= 1) {
        float4 Au, Su;
        Au.x = __shfl_up_sync(0xFFFFFFFFu, Ap.x, d);
        Au.y = __shfl_up_sync(0xFFFFFFFFu, Ap.y, d);
        Au.z = __shfl_up_sync(0xFFFFFFFFu, Ap.z, d);
        Au.w = __shfl_up_sync(0xFFFFFFFFu, Ap.w, d);
        Su.x = __shfl_up_sync(0xFFFFFFFFu, Sp.x, d);
        Su.y = __shfl_up_sync(0xFFFFFFFFu, Sp.y, d);
        Su.z = __shfl_up_sync(0xFFFFFFFFu, Sp.z, d);
        Su.w = __shfl_up_sync(0xFFFFFFFFu, Sp.w, d);
        if (lane >= d) {
            Sp.x = Ap.x*Su.x + Sp.x;  Ap.x *= Au.x;
            Sp.y = Ap.y*Su.y + Sp.y;  Ap.y *= Au.y;
            Sp.z = Ap.z*Su.z + Sp.z;  Ap.z *= Au.z;
            Sp.w = Ap.w*Su.w + Sp.w;  Ap.w *= Au.w;
        }
    }

    float4 Ae, Se;
    Ae.x = __shfl_up_sync(0xFFFFFFFFu, Ap.x, 1);
    Ae.y = __shfl_up_sync(0xFFFFFFFFu, Ap.y, 1);
    Ae.z = __shfl_up_sync(0xFFFFFFFFu, Ap.z, 1);
    Ae.w = __shfl_up_sync(0xFFFFFFFFu, Ap.w, 1);
    Se.x = __shfl_up_sync(0xFFFFFFFFu, Sp.x, 1);
    Se.y = __shfl_up_sync(0xFFFFFFFFu, Sp.y, 1);
    Se.z = __shfl_up_sync(0xFFFFFFFFu, Sp.z, 1);
    Se.w = __shfl_up_sync(0xFFFFFFFFu, Sp.w, 1);
    if (lane == 0) {
        Ae = make_float4(1.f,1.f,1.f,1.f);
        Se = make_float4(0.f,0.f,0.f,0.f);
    }

    const float4 v = reinterpret_cast<const float4*>(h0)[b * 128 + h4];
    float4 st;
    st.x = (v.x >= 0.f) ? (v.x + 0.5f) : sigmoidf_(v.x);
    st.y = (v.y >= 0.f) ? (v.y + 0.5f) : sigmoidf_(v.y);
    st.z = (v.z >= 0.f) ? (v.z + 0.5f) : sigmoidf_(v.z);
    st.w = (v.w >= 0.f) ? (v.w + 0.5f) : sigmoidf_(v.w);

    st.x = Ae.x*st.x + Se.x;
    st.y = Ae.y*st.y + Se.y;
    st.z = Ae.z*st.z + Se.z;
    st.w = Ae.w*st.w + Se.w;

    #pragma unroll
    for (int i = 0; i < 4; i++) {
        Hb4[ob + i * 128] = st;
        st.x = Ai[i].x*st.x + Si[i].x;
        st.y = Ai[i].y*st.y + Si[i].y;
        st.z = Ai[i].z*st.z + Si[i].z;
        st.w = Ai[i].w*st.w + Si[i].w;
    }
}

// ----------------------------- scan phase C: rescan + output -----------------------------
__global__ __launch_bounds__(256) void scan_phaseC(float* __restrict__ out)
{
    const int idx = blockIdx.x * 256 + threadIdx.x;     // 0 .. 131071
    const int h4 = idx & 127;
    const int ch = (idx >> 7) & (NC - 1);
    const int b  = idx >> 14;
    const uint4* CG4 = reinterpret_cast<const uint4*>(g_CG);
    float4* O4 = reinterpret_cast<float4*>(out);
    size_t p = ((size_t)(b * T_ + ch * LC) * H_) / 4 + h4;

    float4 st = reinterpret_cast<const float4*>(g_Hb)[(b * NC + ch) * 128 + h4];
    #pragma unroll 4
    for (int t = 0; t < LC; t++, p += H_/4) {
        const uint4 u = CG4[p];
        const float2 a0 = __half22float2(*reinterpret_cast<const __half2*>(&u.x));
        const float2 a1 = __half22float2(*reinterpret_cast<const __half2*>(&u.y));
        const float2 a2 = __half22float2(*reinterpret_cast<const __half2*>(&u.z));
        const float2 a3 = __half22float2(*reinterpret_cast<const __half2*>(&u.w));
        st.x = a0.x*st.x + (1.f-a0.x)*a0.y;
        st.y = a1.x*st.y + (1.f-a1.x)*a1.y;
        st.z = a2.x*st.z + (1.f-a2.x)*a2.y;
        st.w = a3.x*st.w + (1.f-a3.x)*a3.y;
        O4[p] = st;
    }
}

extern "C" void kernel_launch(void* const* d_in, const int* in_sizes, int n_in,
                              void* d_out, int out_size)
{
    const float* x  = (const float*)d_in[0];
    const float* h0 = (const float*)d_in[1];
    const float* Wz = (const float*)d_in[2];
    const float* bz = (const float*)d_in[3];
    const float* Wh = (const float*)d_in[4];
    const float* bh = (const float*)d_in[5];
    float* out = (float*)d_out;

    cudaFuncSetAttribute(gemm_act_kernel, cudaFuncAttributeMaxDynamicSharedMemorySize, GEMM_SMEM);

    prep_kernel<<<(XBLOCKS + WPAIRS) / 8, 256>>>(x, Wz, Wh);
    gemm_act_kernel<<<dim3(8, 256), 256, GEMM_SMEM>>>(bz, bh);
    scan_phaseB<<<128, 256>>>(h0);
    scan_phaseC<<<512, 256>>>(out);
}